// round 14
// baseline (speedup 1.0000x reference)
#include <cuda_runtime.h>
#include <cuda_fp16.h>
#include <float.h>

#define NTILES    1024
#define GRID_MAIN 304
#define MARGIN    6.0e-5f

// ---- main smem layout (bytes); rows padded to 144B (72 fp16) for ldmatrix ----
#define OFF_XH   0        // 128 x 144B  x fp16
#define OFF_EH   18432    // 128 x 144B  codebook fp16 chunk (scaled by 2^10)
#define OFF_ESQ  36864    // 1024 f32
#define OFF_CTRL 40960    // s_tile
#define OFF_IDX  41088    // 128 ints (per-row phase-1 idx)
#define OFF_STG  41600    // 128x128 f32 x staging (64 KB)
#define SMEM_MAIN 107136
// epilogue reuse (inside dead xh/eh region): qs [128][65] f32 at 0, red at 33536

__device__ float   g_esq[1024];
__device__ __align__(16) __half g_cbh[1024 * 64];   // [k][c] fp16, scaled 2^10
__device__ int     g_idx_arr[131072];
__device__ int     g_i2_arr[131072];
__device__ int     g_pair_rows[131072];
__device__ int     g_full_rows[131072];
__device__ int     g_pair_cnt, g_full_cnt, g_tile;
__device__ double  g_part[NTILES];

// ---------------- helpers ----------------
__device__ __forceinline__ unsigned su32(const void* p) {
    return (unsigned)__cvta_generic_to_shared(p);
}
__device__ __forceinline__ void cp16(unsigned dst, const void* src) {
    asm volatile("cp.async.cg.shared.global [%0], [%1], 16;" :: "r"(dst), "l"(src));
}
__device__ __forceinline__ void cp_commit() { asm volatile("cp.async.commit_group;"); }
template <int N> __device__ __forceinline__ void cp_wait() {
    asm volatile("cp.async.wait_group %0;" :: "n"(N));
}
__device__ __forceinline__ void ldm4(unsigned* r, unsigned addr) {
    asm volatile("ldmatrix.sync.aligned.m8n8.x4.shared.b16 {%0,%1,%2,%3}, [%4];"
                 : "=r"(r[0]), "=r"(r[1]), "=r"(r[2]), "=r"(r[3]) : "r"(addr));
}
__device__ __forceinline__ void mma16816(float* c, const unsigned* a, const unsigned* b) {
    asm volatile(
        "mma.sync.aligned.m16n8k16.row.col.f32.f16.f16.f32 "
        "{%0,%1,%2,%3}, {%4,%5,%6,%7}, {%8,%9}, {%0,%1,%2,%3};"
        : "+f"(c[0]), "+f"(c[1]), "+f"(c[2]), "+f"(c[3])
        : "r"(a[0]), "r"(a[1]), "r"(a[2]), "r"(a[3]), "r"(b[0]), "r"(b[1]));
}
// Packed-score top-3 insert: 5 min/max ops, indices ride in low 10 bits.
__device__ __forceinline__ void ins3(float& m1, float& m2, float& m3, float sc) {
    float t1 = fmaxf(sc, m1);
    m1 = fminf(sc, m1);
    float t2 = fmaxf(t1, m2);
    m2 = fminf(t1, m2);
    m3 = fminf(t2, m3);
}
__device__ __forceinline__ float packsc(float sc, int k) {
    return __uint_as_float((__float_as_uint(sc) & 0xFFFFFC00u) | (unsigned)k);
}

// ---------------- prep (vectorized, 4 elems/thread) ----------------
__global__ void vq_prep(const float* __restrict__ cb) {
    int gid = blockIdx.x * 256 + threadIdx.x;        // 16384 threads
    if (gid == 0) { g_tile = 0; g_pair_cnt = 0; g_full_cnt = 0; }
    {
        float4 v = *(const float4*)(cb + gid * 4);
        __half2 h01 = __floats2half2_rn(v.x * 1024.0f, v.y * 1024.0f);
        __half2 h23 = __floats2half2_rn(v.z * 1024.0f, v.w * 1024.0f);
        *(uint2*)(g_cbh + gid * 4) =
            make_uint2(*(unsigned*)&h01, *(unsigned*)&h23);
    }
    if (gid < 1024) {
        const float* row = cb + gid * 64;
        float s = 0.f;
        #pragma unroll
        for (int c = 0; c < 64; ++c) s = __fadd_rn(s, __fmul_rn(row[c], row[c]));
        g_esq[gid] = s;
    }
}

// ---------------- main: fp16 HMMA argmin + fused z_q/mse epilogue ----------------
__global__ void __launch_bounds__(256, 2)
vq_main(const float* __restrict__ x, const float* __restrict__ cb,
        float* __restrict__ out) {
    extern __shared__ char sm[];
    const unsigned sb32 = su32(sm);
    float* esq_sh = (float*)(sm + OFF_ESQ);
    int*   ctrl   = (int*)(sm + OFF_CTRL);
    int*   idx_sh = (int*)(sm + OFF_IDX);

    const int tid  = threadIdx.x;
    const int wid  = tid >> 5;
    const int lane = tid & 31;
    const int rs   = lane & 7;
    const int g1   = (lane >> 3) & 1;
    const int g2   = (lane >> 4) & 1;
    const int qp   = lane & 3;
    const int qr   = lane >> 2;

    const unsigned aoff = (unsigned)((wid * 16 + rs + g1 * 8) * 144 + g2 * 16);
    const unsigned boff = (unsigned)((rs + g2 * 8) * 144 + g1 * 16);

    for (int i = tid; i < 1024; i += 256) esq_sh[i] = g_esq[i];

    while (true) {
        if (tid == 0) ctrl[0] = atomicAdd(&g_tile, 1);
        __syncthreads();
        const int tile = ctrl[0];
        if (tile >= NTILES) return;
        const int b  = tile >> 5;
        const int sp = (tile & 31) * 128;
        const float* xbase = x + (size_t)b * 262144 + sp;

        // ---- stage x fp32 coalesced, kick eh chunk 0 ----
        #pragma unroll
        for (int i = 0; i < 8; ++i) {
            int lin = i * 256 + tid;
            int c = lin >> 5, f4 = (lin & 31) << 2;
            cp16(sb32 + OFF_STG + (c * 128 + f4) * 4, xbase + (size_t)c * 4096 + f4);
        }
        cp_commit();
        #pragma unroll
        for (int i = 0; i < 4; ++i) {
            int lin = i * 256 + tid;
            int k = lin >> 3, part = lin & 7;
            cp16(sb32 + OFF_EH + k * 144 + part * 16,
                 (const char*)g_cbh + (size_t)(k * 64 + part * 8) * 2);
        }
        cp_commit();
        cp_wait<1>();
        __syncthreads();

        // ---- convert x -> fp16, [s][c] stride 72 fp16 ----
        {
            const float* stg = (const float*)(sm + OFF_STG);
            const int s = tid >> 1, ch0 = (tid & 1) * 32;
            char* ph = sm + OFF_XH + s * 144 + ch0 * 2;
            #pragma unroll
            for (int c = 0; c < 32; c += 2) {
                float v0 = stg[(ch0 + c)     * 128 + s];
                float v1 = stg[(ch0 + c + 1) * 128 + s];
                __half2 h2 = __floats2half2_rn(v0, v1);
                *(unsigned*)(ph + c * 2) = *(unsigned*)&h2;
            }
        }

        float m1A = FLT_MAX, m2A = FLT_MAX, m3A = FLT_MAX;
        float m1B = FLT_MAX, m2B = FLT_MAX, m3B = FLT_MAX;

        for (int chunk = 0; chunk < 8; ++chunk) {
            cp_wait<0>();
            __syncthreads();

            float acc[16][4];
            #pragma unroll
            for (int s16 = 0; s16 < 16; ++s16)
                #pragma unroll
                for (int q = 0; q < 4; ++q) acc[s16][q] = 0.f;

            #pragma unroll
            for (int ks = 0; ks < 4; ++ks) {
                unsigned ah[4];
                ldm4(ah, sb32 + OFF_XH + aoff + ks * 32);
                #pragma unroll
                for (int np = 0; np < 8; ++np) {
                    unsigned bh[4];
                    ldm4(bh, sb32 + OFF_EH + boff + np * (16 * 144) + ks * 32);
                    mma16816(acc[np * 2],     ah, bh);
                    mma16816(acc[np * 2 + 1], ah, bh + 2);
                }
            }
            __syncthreads();

            if (chunk < 7) {
                const char* gh = (const char*)g_cbh + (size_t)(chunk + 1) * 8192 * 2;
                #pragma unroll
                for (int i = 0; i < 4; ++i) {
                    int lin = i * 256 + tid;
                    int k = lin >> 3, part = lin & 7;
                    cp16(sb32 + OFF_EH + k * 144 + part * 16, gh + (k * 64 + part * 8) * 2);
                }
                cp_commit();
            }

            const int cbase = chunk * 128 + qp * 2;
            #pragma unroll
            for (int s16 = 0; s16 < 16; ++s16) {
                const int k0 = cbase + s16 * 8;
                const int k1 = k0 + 1;
                float2 eq = *(float2*)(esq_sh + k0);
                ins3(m1A, m2A, m3A, packsc(__fmaf_rn(-0.001953125f, acc[s16][0], eq.x), k0));
                ins3(m1A, m2A, m3A, packsc(__fmaf_rn(-0.001953125f, acc[s16][1], eq.y), k1));
                ins3(m1B, m2B, m3B, packsc(__fmaf_rn(-0.001953125f, acc[s16][2], eq.x), k0));
                ins3(m1B, m2B, m3B, packsc(__fmaf_rn(-0.001953125f, acc[s16][3], eq.y), k1));
            }
        }

        // ---- quad merge ----
        #pragma unroll
        for (int off = 1; off <= 2; off <<= 1) {
            float o1 = __shfl_xor_sync(0xffffffffu, m1A, off);
            float o2 = __shfl_xor_sync(0xffffffffu, m2A, off);
            float o3 = __shfl_xor_sync(0xffffffffu, m3A, off);
            ins3(m1A, m2A, m3A, o1);
            ins3(m1A, m2A, m3A, o2);
            m3A = fminf(m3A, o3);
            o1 = __shfl_xor_sync(0xffffffffu, m1B, off);
            o2 = __shfl_xor_sync(0xffffffffu, m2B, off);
            o3 = __shfl_xor_sync(0xffffffffu, m3B, off);
            ins3(m1B, m2B, m3B, o1);
            ins3(m1B, m2B, m3B, o2);
            m3B = fminf(m3B, o3);
        }
        // ---- flag appends + smem idx publish ----
        if (qp == 0) {
            const unsigned GM = 0x11111111u;
            const unsigned mlt = ((1u << lane) - 1) & GM;
            int rowL = wid * 16 + qr;
            int rowA = tile * 128 + rowL;
            int rowB = rowA + 8;
            int iA1 = (int)(__float_as_uint(m1A) & 1023u);
            int iB1 = (int)(__float_as_uint(m1B) & 1023u);
            g_idx_arr[rowA] = iA1;
            g_idx_arr[rowB] = iB1;
            idx_sh[rowL]     = iA1;
            idx_sh[rowL + 8] = iB1;
            bool fA = (m3A - m1A < MARGIN);
            bool pA = !fA && (m2A - m1A < MARGIN);
            bool fB = (m3B - m1B < MARGIN);
            bool pB = !fB && (m2B - m1B < MARGIN);
            if (pA) g_i2_arr[rowA] = (int)(__float_as_uint(m2A) & 1023u);
            if (pB) g_i2_arr[rowB] = (int)(__float_as_uint(m2B) & 1023u);

            unsigned bfA = __ballot_sync(GM, fA), bpA = __ballot_sync(GM, pA);
            unsigned bfB = __ballot_sync(GM, fB), bpB = __ballot_sync(GM, pB);
            int baseF = 0, baseP = 0;
            if (lane == 0) {
                int nF = __popc(bfA) + __popc(bfB);
                int nP = __popc(bpA) + __popc(bpB);
                if (nF) baseF = atomicAdd(&g_full_cnt, nF);
                if (nP) baseP = atomicAdd(&g_pair_cnt, nP);
            }
            baseF = __shfl_sync(GM, baseF, 0);
            baseP = __shfl_sync(GM, baseP, 0);
            if (fA) g_full_rows[baseF + __popc(bfA & mlt)] = rowA;
            if (fB) g_full_rows[baseF + __popc(bfA) + __popc(bfB & mlt)] = rowB;
            if (pA) g_pair_rows[baseP + __popc(bpA & mlt)] = rowA;
            if (pB) g_pair_rows[baseP + __popc(bpA) + __popc(bpB & mlt)] = rowB;
        }
        __syncthreads();     // idx_sh ready; xh/eh now dead -> reuse for qs

        // ---- fused epilogue: gather cb rows, write z_q, mse partial ----
        {
            float* qs  = (float*)sm;                 // [128][65] f32 (33280 B)
            float* red = (float*)(sm + 33536);       // [256] f32
            #pragma unroll
            for (int i = 0; i < 8; ++i) {
                int lin = i * 256 + tid;             // 2048 float4 chunks
                int row = lin >> 4, seg = lin & 15;
                float4 v = *(const float4*)(cb + (size_t)idx_sh[row] * 64 + seg * 4);
                float* d = qs + row * 65 + seg * 4;
                d[0] = v.x; d[1] = v.y; d[2] = v.z; d[3] = v.w;
            }
            __syncthreads();

            const float* stg = (const float*)(sm + OFF_STG);
            float fsum = 0.f;
            const size_t obase = (size_t)b * 262144 + sp;
            #pragma unroll
            for (int it = 0; it < 32; ++it) {
                int lin = it * 256 + tid;
                int c = lin >> 7, s = lin & 127;
                float q  = qs[s * 65 + c];
                float xv = stg[c * 128 + s];
                out[obase + (size_t)c * 4096 + s] = q;
                float d = xv - q;
                fsum = __fmaf_rn(d, d, fsum);
            }
            red[tid] = fsum;
            __syncthreads();
            for (int off = 128; off > 0; off >>= 1) {
                if (tid < off) red[tid] = __fadd_rn(red[tid], red[tid + off]);
                __syncthreads();
            }
            if (tid == 0) g_part[tile] = (double)red[0];
        }
        __syncthreads();     // smem reuse fence for next tile
    }
}

// ---------------- fixup: exact resolve of flagged rows + z_q/mse patch ----------------
__global__ void __launch_bounds__(256, 2)
vq_fixup(const float* __restrict__ x, const float* __restrict__ cb,
         float* __restrict__ out) {
    const int tid = threadIdx.x;

    // ---- phase A: pair rows (thread per row), exact ref arithmetic ----
    const int nP = g_pair_cnt;
    for (int i = blockIdx.x * 256 + tid; i < nP; i += gridDim.x * 256) {
        int row = g_pair_rows[i];
        int b = row >> 12, s = row & 4095;
        const float* xp = x + (size_t)b * 262144 + s;
        float xr[64];
        #pragma unroll
        for (int c = 0; c < 64; ++c) xr[c] = __ldg(xp + (size_t)c * 4096);
        float xsq = 0.f;
        #pragma unroll
        for (int c = 0; c < 64; ++c) xsq = __fadd_rn(xsq, __fmul_rn(xr[c], xr[c]));

        int k1 = g_idx_arr[row], k2 = g_i2_arr[row];
        float d1 = 0.f, d2 = 0.f;
        const float* r1 = cb + (size_t)k1 * 64;
        const float* r2 = cb + (size_t)k2 * 64;
        #pragma unroll
        for (int c = 0; c < 64; ++c) {
            d1 = __fmaf_rn(xr[c], __ldg(r1 + c), d1);
            d2 = __fmaf_rn(xr[c], __ldg(r2 + c), d2);
        }
        float s1 = __fsub_rn(__fadd_rn(xsq, __ldg(g_esq + k1)), __fmul_rn(2.f, d1));
        float s2 = __fsub_rn(__fadd_rn(xsq, __ldg(g_esq + k2)), __fmul_rn(2.f, d2));
        if (s2 < s1 || (s2 == s1 && k2 < k1)) {
            g_idx_arr[row] = k2;
            float delta = 0.f;
            float* op = out + (size_t)b * 262144 + s;
            #pragma unroll
            for (int c = 0; c < 64; ++c) {
                float qn = __ldg(r2 + c), qo = __ldg(r1 + c);
                float dn = xr[c] - qn, do_ = xr[c] - qo;
                delta += dn * dn - do_ * do_;
                op[(size_t)c * 4096] = qn;
            }
            atomicAdd(&g_part[row >> 7], (double)delta);
        }
    }

    // ---- phase B: full rows (block per row), exact ref arithmetic ----
    __shared__ float xrow[64];
    __shared__ float rv[256];
    __shared__ int   rk[256];
    __shared__ float dred[64];
    __shared__ int   s_old, s_new;
    const int nF = g_full_cnt;

    for (int i = blockIdx.x; i < nF; i += gridDim.x) {
        int row = g_full_rows[i];
        int b = row >> 12, s = row & 4095;
        if (tid < 64) xrow[tid] = __ldg(x + (size_t)b * 262144 + (size_t)tid * 4096 + s);
        __syncthreads();

        float xsq = 0.f;
        #pragma unroll
        for (int c = 0; c < 64; ++c)
            xsq = __fadd_rn(xsq, __fmul_rn(xrow[c], xrow[c]));

        float bv = FLT_MAX; int bk = 0;
        #pragma unroll
        for (int j = 0; j < 4; ++j) {
            int k = tid * 4 + j;
            const float* e = cb + (size_t)k * 64;
            float dot = 0.f;
            #pragma unroll
            for (int c4 = 0; c4 < 16; ++c4) {
                float4 ev = *(const float4*)(e + c4 * 4);
                dot = __fmaf_rn(xrow[c4 * 4 + 0], ev.x, dot);
                dot = __fmaf_rn(xrow[c4 * 4 + 1], ev.y, dot);
                dot = __fmaf_rn(xrow[c4 * 4 + 2], ev.z, dot);
                dot = __fmaf_rn(xrow[c4 * 4 + 3], ev.w, dot);
            }
            float d2 = __fsub_rn(__fadd_rn(xsq, __ldg(g_esq + k)), __fmul_rn(2.f, dot));
            if (d2 < bv) { bv = d2; bk = k; }
        }
        rv[tid] = bv; rk[tid] = bk;
        __syncthreads();
        for (int off = 128; off > 0; off >>= 1) {
            if (tid < off) {
                float ov = rv[tid + off]; int ok = rk[tid + off];
                if (ov < rv[tid] || (ov == rv[tid] && ok < rk[tid])) {
                    rv[tid] = ov; rk[tid] = ok;
                }
            }
            __syncthreads();
        }
        if (tid == 0) {
            s_old = g_idx_arr[row];
            s_new = rk[0];
            if (s_new != s_old) g_idx_arr[row] = s_new;
        }
        __syncthreads();
        if (s_new != s_old) {
            if (tid < 64) {
                float qn = __ldg(cb + (size_t)s_new * 64 + tid);
                float qo = __ldg(cb + (size_t)s_old * 64 + tid);
                out[(size_t)b * 262144 + (size_t)tid * 4096 + s] = qn;
                float dn = xrow[tid] - qn, dol = xrow[tid] - qo;
                dred[tid] = dn * dn - dol * dol;
            }
            __syncthreads();
            if (tid == 0) {
                float delta = 0.f;
                #pragma unroll
                for (int c = 0; c < 64; ++c) delta += dred[c];
                atomicAdd(&g_part[row >> 7], (double)delta);
            }
        }
        __syncthreads();
    }
}

__global__ void vq_loss(float* loss_out) {
    __shared__ double sh[256];
    double s = 0.0;
    for (int i = threadIdx.x; i < NTILES; i += 256) s += g_part[i];
    sh[threadIdx.x] = s;
    __syncthreads();
    for (int off = 128; off > 0; off >>= 1) {
        if (threadIdx.x < off) sh[threadIdx.x] += sh[threadIdx.x + off];
        __syncthreads();
    }
    if (threadIdx.x == 0) {
        float m = (float)(sh[0] / 8388608.0);
        loss_out[0] = __fadd_rn(m, __fmul_rn(0.25f, m));
    }
}

extern "C" void kernel_launch(void* const* d_in, const int* in_sizes, int n_in,
                              void* d_out, int out_size) {
    const float* x  = (const float*)d_in[0];
    const float* cb = (const float*)d_in[1];
    float* out = (float*)d_out;

    cudaFuncSetAttribute(vq_main, cudaFuncAttributeMaxDynamicSharedMemorySize, SMEM_MAIN);
    vq_prep<<<64, 256>>>(cb);
    vq_main<<<GRID_MAIN, 256, SMEM_MAIN>>>(x, cb, out);
    vq_fixup<<<512, 256>>>(x, cb, out);
    vq_loss<<<1, 256>>>(out + (out_size - 1));
}

// round 15
// speedup vs baseline: 1.0227x; 1.0227x over previous
#include <cuda_runtime.h>
#include <cuda_fp16.h>
#include <float.h>

#define NTILES    1024
#define GRID_MAIN 304
#define GRID_FIX  512
#define MARGIN    6.0e-5f

// ---- main smem layout (bytes); rows padded to 144B (72 fp16) for ldmatrix ----
#define OFF_XH   0        // 128 x 144B  x fp16
#define OFF_EH   18432    // 128 x 144B  codebook fp16 chunk (scaled by 2^10)
#define OFF_ESQ  36864    // 1024 f32
#define OFF_CTRL 40960    // s_tile
#define OFF_IDX  41088    // 128 ints
#define SMEM_MAIN 41600
// epilogue reuse inside dead xh/eh region: qs [128][65] f32 at 0, red at 33536

__device__ float   g_esq[1024];
__device__ __align__(16) __half g_cbh[1024 * 64];   // [k][c] fp16, scaled 2^10
__device__ int     g_idx_arr[131072];
__device__ int     g_i2_arr[131072];
__device__ int     g_pair_rows[131072];
__device__ int     g_full_rows[131072];
__device__ int     g_pair_cnt, g_full_cnt, g_tile, g_done;
__device__ double  g_part[NTILES];

// ---------------- helpers ----------------
__device__ __forceinline__ unsigned su32(const void* p) {
    return (unsigned)__cvta_generic_to_shared(p);
}
__device__ __forceinline__ void cp16(unsigned dst, const void* src) {
    asm volatile("cp.async.cg.shared.global [%0], [%1], 16;" :: "r"(dst), "l"(src));
}
__device__ __forceinline__ void cp_commit() { asm volatile("cp.async.commit_group;"); }
template <int N> __device__ __forceinline__ void cp_wait() {
    asm volatile("cp.async.wait_group %0;" :: "n"(N));
}
__device__ __forceinline__ void ldm4(unsigned* r, unsigned addr) {
    asm volatile("ldmatrix.sync.aligned.m8n8.x4.shared.b16 {%0,%1,%2,%3}, [%4];"
                 : "=r"(r[0]), "=r"(r[1]), "=r"(r[2]), "=r"(r[3]) : "r"(addr));
}
__device__ __forceinline__ void mma16816(float* c, const unsigned* a, const unsigned* b) {
    asm volatile(
        "mma.sync.aligned.m16n8k16.row.col.f32.f16.f16.f32 "
        "{%0,%1,%2,%3}, {%4,%5,%6,%7}, {%8,%9}, {%0,%1,%2,%3};"
        : "+f"(c[0]), "+f"(c[1]), "+f"(c[2]), "+f"(c[3])
        : "r"(a[0]), "r"(a[1]), "r"(a[2]), "r"(a[3]), "r"(b[0]), "r"(b[1]));
}
__device__ __forceinline__ void ins3(float& m1, float& m2, float& m3, float sc) {
    float t1 = fmaxf(sc, m1);
    m1 = fminf(sc, m1);
    float t2 = fmaxf(t1, m2);
    m2 = fminf(t1, m2);
    m3 = fminf(t2, m3);
}
__device__ __forceinline__ float packsc(float sc, int k) {
    return __uint_as_float((__float_as_uint(sc) & 0xFFFFFC00u) | (unsigned)k);
}

// ---------------- prep (vectorized, 4 elems/thread) ----------------
__global__ void vq_prep(const float* __restrict__ cb) {
    int gid = blockIdx.x * 256 + threadIdx.x;        // 16384 threads
    if (gid == 0) { g_tile = 0; g_pair_cnt = 0; g_full_cnt = 0; g_done = 0; }
    {
        float4 v = *(const float4*)(cb + gid * 4);
        __half2 h01 = __floats2half2_rn(v.x * 1024.0f, v.y * 1024.0f);
        __half2 h23 = __floats2half2_rn(v.z * 1024.0f, v.w * 1024.0f);
        *(uint2*)(g_cbh + gid * 4) =
            make_uint2(*(unsigned*)&h01, *(unsigned*)&h23);
    }
    if (gid < 1024) {
        const float* row = cb + gid * 64;
        float s = 0.f;
        #pragma unroll
        for (int c = 0; c < 64; ++c) s = __fadd_rn(s, __fmul_rn(row[c], row[c]));
        g_esq[gid] = s;
    }
}

// ---------------- main: fp16 HMMA argmin + fused z_q/mse epilogue ----------------
__global__ void __launch_bounds__(256, 2)
vq_main(const float* __restrict__ x, const float* __restrict__ cb,
        float* __restrict__ out) {
    extern __shared__ char sm[];
    const unsigned sb32 = su32(sm);
    float* esq_sh = (float*)(sm + OFF_ESQ);
    int*   ctrl   = (int*)(sm + OFF_CTRL);
    int*   idx_sh = (int*)(sm + OFF_IDX);

    const int tid  = threadIdx.x;
    const int wid  = tid >> 5;
    const int lane = tid & 31;
    const int rs   = lane & 7;
    const int g1   = (lane >> 3) & 1;
    const int g2   = (lane >> 4) & 1;
    const int qp   = lane & 3;
    const int qr   = lane >> 2;

    const unsigned aoff = (unsigned)((wid * 16 + rs + g1 * 8) * 144 + g2 * 16);
    const unsigned boff = (unsigned)((rs + g2 * 8) * 144 + g1 * 16);

    for (int i = tid; i < 1024; i += 256) esq_sh[i] = g_esq[i];

    while (true) {
        if (tid == 0) ctrl[0] = atomicAdd(&g_tile, 1);
        __syncthreads();
        const int tile = ctrl[0];
        if (tile >= NTILES) return;
        const int b  = tile >> 5;
        const int sp = (tile & 31) * 128;
        const float* xbase = x + (size_t)b * 262144 + sp;

        // ---- kick eh chunk 0 ----
        #pragma unroll
        for (int i = 0; i < 4; ++i) {
            int lin = i * 256 + tid;
            int k = lin >> 3, part = lin & 7;
            cp16(sb32 + OFF_EH + k * 144 + part * 16,
                 (const char*)g_cbh + (size_t)(k * 64 + part * 8) * 2);
        }
        cp_commit();

        // ---- convert x -> fp16 directly from gmem (coalesced 64B spans) ----
        {
            const int s = tid >> 1, ch0 = (tid & 1) * 32;
            char* ph = sm + OFF_XH + s * 144 + ch0 * 2;
            #pragma unroll
            for (int c = 0; c < 32; c += 2) {
                float v0 = __ldg(xbase + (size_t)(ch0 + c) * 4096 + s);
                float v1 = __ldg(xbase + (size_t)(ch0 + c + 1) * 4096 + s);
                __half2 h2 = __floats2half2_rn(v0, v1);
                *(unsigned*)(ph + c * 2) = *(unsigned*)&h2;
            }
        }

        float m1A = FLT_MAX, m2A = FLT_MAX, m3A = FLT_MAX;
        float m1B = FLT_MAX, m2B = FLT_MAX, m3B = FLT_MAX;

        for (int chunk = 0; chunk < 8; ++chunk) {
            cp_wait<0>();
            __syncthreads();     // eh ready; xh stores visible (chunk 0)

            float acc[16][4];
            #pragma unroll
            for (int s16 = 0; s16 < 16; ++s16)
                #pragma unroll
                for (int q = 0; q < 4; ++q) acc[s16][q] = 0.f;

            #pragma unroll
            for (int ks = 0; ks < 4; ++ks) {
                unsigned ah[4];
                ldm4(ah, sb32 + OFF_XH + aoff + ks * 32);
                #pragma unroll
                for (int np = 0; np < 8; ++np) {
                    unsigned bh[4];
                    ldm4(bh, sb32 + OFF_EH + boff + np * (16 * 144) + ks * 32);
                    mma16816(acc[np * 2],     ah, bh);
                    mma16816(acc[np * 2 + 1], ah, bh + 2);
                }
            }
            __syncthreads();

            if (chunk < 7) {
                const char* gh = (const char*)g_cbh + (size_t)(chunk + 1) * 8192 * 2;
                #pragma unroll
                for (int i = 0; i < 4; ++i) {
                    int lin = i * 256 + tid;
                    int k = lin >> 3, part = lin & 7;
                    cp16(sb32 + OFF_EH + k * 144 + part * 16, gh + (k * 64 + part * 8) * 2);
                }
                cp_commit();
            }

            const int cbase = chunk * 128 + qp * 2;
            #pragma unroll
            for (int s16 = 0; s16 < 16; ++s16) {
                const int k0 = cbase + s16 * 8;
                const int k1 = k0 + 1;
                float2 eq = *(float2*)(esq_sh + k0);
                ins3(m1A, m2A, m3A, packsc(__fmaf_rn(-0.001953125f, acc[s16][0], eq.x), k0));
                ins3(m1A, m2A, m3A, packsc(__fmaf_rn(-0.001953125f, acc[s16][1], eq.y), k1));
                ins3(m1B, m2B, m3B, packsc(__fmaf_rn(-0.001953125f, acc[s16][2], eq.x), k0));
                ins3(m1B, m2B, m3B, packsc(__fmaf_rn(-0.001953125f, acc[s16][3], eq.y), k1));
            }
        }

        // ---- quad merge ----
        #pragma unroll
        for (int off = 1; off <= 2; off <<= 1) {
            float o1 = __shfl_xor_sync(0xffffffffu, m1A, off);
            float o2 = __shfl_xor_sync(0xffffffffu, m2A, off);
            float o3 = __shfl_xor_sync(0xffffffffu, m3A, off);
            ins3(m1A, m2A, m3A, o1);
            ins3(m1A, m2A, m3A, o2);
            m3A = fminf(m3A, o3);
            o1 = __shfl_xor_sync(0xffffffffu, m1B, off);
            o2 = __shfl_xor_sync(0xffffffffu, m2B, off);
            o3 = __shfl_xor_sync(0xffffffffu, m3B, off);
            ins3(m1B, m2B, m3B, o1);
            ins3(m1B, m2B, m3B, o2);
            m3B = fminf(m3B, o3);
        }
        // ---- flag appends + smem idx publish ----
        if (qp == 0) {
            const unsigned GM = 0x11111111u;
            const unsigned mlt = ((1u << lane) - 1) & GM;
            int rowL = wid * 16 + qr;
            int rowA = tile * 128 + rowL;
            int rowB = rowA + 8;
            int iA1 = (int)(__float_as_uint(m1A) & 1023u);
            int iB1 = (int)(__float_as_uint(m1B) & 1023u);
            g_idx_arr[rowA] = iA1;
            g_idx_arr[rowB] = iB1;
            idx_sh[rowL]     = iA1;
            idx_sh[rowL + 8] = iB1;
            bool fA = (m3A - m1A < MARGIN);
            bool pA = !fA && (m2A - m1A < MARGIN);
            bool fB = (m3B - m1B < MARGIN);
            bool pB = !fB && (m2B - m1B < MARGIN);
            if (pA) g_i2_arr[rowA] = (int)(__float_as_uint(m2A) & 1023u);
            if (pB) g_i2_arr[rowB] = (int)(__float_as_uint(m2B) & 1023u);

            unsigned bfA = __ballot_sync(GM, fA), bpA = __ballot_sync(GM, pA);
            unsigned bfB = __ballot_sync(GM, fB), bpB = __ballot_sync(GM, pB);
            int baseF = 0, baseP = 0;
            if (lane == 0) {
                int nF = __popc(bfA) + __popc(bfB);
                int nP = __popc(bpA) + __popc(bpB);
                if (nF) baseF = atomicAdd(&g_full_cnt, nF);
                if (nP) baseP = atomicAdd(&g_pair_cnt, nP);
            }
            baseF = __shfl_sync(GM, baseF, 0);
            baseP = __shfl_sync(GM, baseP, 0);
            if (fA) g_full_rows[baseF + __popc(bfA & mlt)] = rowA;
            if (fB) g_full_rows[baseF + __popc(bfA) + __popc(bfB & mlt)] = rowB;
            if (pA) g_pair_rows[baseP + __popc(bpA & mlt)] = rowA;
            if (pB) g_pair_rows[baseP + __popc(bpA) + __popc(bpB & mlt)] = rowB;
        }
        __syncthreads();     // idx_sh ready; xh/eh now dead -> reuse for qs

        // ---- fused epilogue: gather cb rows, write z_q, mse partial ----
        {
            float* qs  = (float*)sm;                 // [128][65] f32
            float* red = (float*)(sm + 33536);       // [256] f32
            #pragma unroll
            for (int i = 0; i < 8; ++i) {
                int lin = i * 256 + tid;
                int row = lin >> 4, seg = lin & 15;
                float4 v = *(const float4*)(cb + (size_t)idx_sh[row] * 64 + seg * 4);
                float* d = qs + row * 65 + seg * 4;
                d[0] = v.x; d[1] = v.y; d[2] = v.z; d[3] = v.w;
            }
            __syncthreads();

            float fsum = 0.f;
            const size_t obase = (size_t)b * 262144 + sp;
            #pragma unroll
            for (int it = 0; it < 32; ++it) {
                int lin = it * 256 + tid;
                int c = lin >> 7, s = lin & 127;
                float q  = qs[s * 65 + c];
                float xv = __ldg(x + obase + (size_t)c * 4096 + s);  // L2-hot
                out[obase + (size_t)c * 4096 + s] = q;
                float d = xv - q;
                fsum = __fmaf_rn(d, d, fsum);
            }
            red[tid] = fsum;
            __syncthreads();
            for (int off = 128; off > 0; off >>= 1) {
                if (tid < off) red[tid] = __fadd_rn(red[tid], red[tid + off]);
                __syncthreads();
            }
            if (tid == 0) g_part[tile] = (double)red[0];
        }
        __syncthreads();     // smem reuse fence for next tile
    }
}

// ---------------- fixup: exact resolve + z_q/mse patch + final loss ----------------
__global__ void __launch_bounds__(256, 2)
vq_fixup(const float* __restrict__ x, const float* __restrict__ cb,
         float* __restrict__ loss_out) {
    const int tid = threadIdx.x;
    float* out = loss_out - 8388608;     // z_q base (loss is last element)

    // ---- phase A: pair rows (thread per row), exact ref arithmetic ----
    const int nP = g_pair_cnt;
    for (int i = blockIdx.x * 256 + tid; i < nP; i += GRID_FIX * 256) {
        int row = g_pair_rows[i];
        int b = row >> 12, s = row & 4095;
        const float* xp = x + (size_t)b * 262144 + s;
        float xr[64];
        #pragma unroll
        for (int c = 0; c < 64; ++c) xr[c] = __ldg(xp + (size_t)c * 4096);
        float xsq = 0.f;
        #pragma unroll
        for (int c = 0; c < 64; ++c) xsq = __fadd_rn(xsq, __fmul_rn(xr[c], xr[c]));

        int k1 = g_idx_arr[row], k2 = g_i2_arr[row];
        float d1 = 0.f, d2 = 0.f;
        const float* r1 = cb + (size_t)k1 * 64;
        const float* r2 = cb + (size_t)k2 * 64;
        #pragma unroll
        for (int c = 0; c < 64; ++c) {
            d1 = __fmaf_rn(xr[c], __ldg(r1 + c), d1);
            d2 = __fmaf_rn(xr[c], __ldg(r2 + c), d2);
        }
        float s1 = __fsub_rn(__fadd_rn(xsq, __ldg(g_esq + k1)), __fmul_rn(2.f, d1));
        float s2 = __fsub_rn(__fadd_rn(xsq, __ldg(g_esq + k2)), __fmul_rn(2.f, d2));
        if (s2 < s1 || (s2 == s1 && k2 < k1)) {
            g_idx_arr[row] = k2;
            float delta = 0.f;
            float* op = out + (size_t)b * 262144 + s;
            #pragma unroll
            for (int c = 0; c < 64; ++c) {
                float qn = __ldg(r2 + c), qo = __ldg(r1 + c);
                float dn = xr[c] - qn, do_ = xr[c] - qo;
                delta += dn * dn - do_ * do_;
                op[(size_t)c * 4096] = qn;
            }
            atomicAdd(&g_part[row >> 7], (double)delta);
        }
    }

    // ---- phase B: full rows (block per row), exact ref arithmetic ----
    __shared__ float xrow[64];
    __shared__ float rv[256];
    __shared__ int   rk[256];
    __shared__ float dred[64];
    __shared__ int   s_old, s_new;
    const int nF = g_full_cnt;

    for (int i = blockIdx.x; i < nF; i += GRID_FIX) {
        int row = g_full_rows[i];
        int b = row >> 12, s = row & 4095;
        if (tid < 64) xrow[tid] = __ldg(x + (size_t)b * 262144 + (size_t)tid * 4096 + s);
        __syncthreads();

        float xsq = 0.f;
        #pragma unroll
        for (int c = 0; c < 64; ++c)
            xsq = __fadd_rn(xsq, __fmul_rn(xrow[c], xrow[c]));

        float bv = FLT_MAX; int bk = 0;
        #pragma unroll
        for (int j = 0; j < 4; ++j) {
            int k = tid * 4 + j;
            const float* e = cb + (size_t)k * 64;
            float dot = 0.f;
            #pragma unroll
            for (int c4 = 0; c4 < 16; ++c4) {
                float4 ev = *(const float4*)(e + c4 * 4);
                dot = __fmaf_rn(xrow[c4 * 4 + 0], ev.x, dot);
                dot = __fmaf_rn(xrow[c4 * 4 + 1], ev.y, dot);
                dot = __fmaf_rn(xrow[c4 * 4 + 2], ev.z, dot);
                dot = __fmaf_rn(xrow[c4 * 4 + 3], ev.w, dot);
            }
            float d2 = __fsub_rn(__fadd_rn(xsq, __ldg(g_esq + k)), __fmul_rn(2.f, dot));
            if (d2 < bv) { bv = d2; bk = k; }
        }
        rv[tid] = bv; rk[tid] = bk;
        __syncthreads();
        for (int off = 128; off > 0; off >>= 1) {
            if (tid < off) {
                float ov = rv[tid + off]; int ok = rk[tid + off];
                if (ov < rv[tid] || (ov == rv[tid] && ok < rk[tid])) {
                    rv[tid] = ov; rk[tid] = ok;
                }
            }
            __syncthreads();
        }
        if (tid == 0) {
            s_old = g_idx_arr[row];
            s_new = rk[0];
            if (s_new != s_old) g_idx_arr[row] = s_new;
        }
        __syncthreads();
        if (s_new != s_old) {
            if (tid < 64) {
                float qn = __ldg(cb + (size_t)s_new * 64 + tid);
                float qo = __ldg(cb + (size_t)s_old * 64 + tid);
                out[(size_t)b * 262144 + (size_t)tid * 4096 + s] = qn;
                float dn = xrow[tid] - qn, dol = xrow[tid] - qo;
                dred[tid] = dn * dn - dol * dol;
            }
            __syncthreads();
            if (tid == 0) {
                float delta = 0.f;
                #pragma unroll
                for (int c = 0; c < 64; ++c) delta += dred[c];
                atomicAdd(&g_part[row >> 7], (double)delta);
            }
        }
        __syncthreads();
    }

    // ---- last-block loss reduction (no separate kernel) ----
    __shared__ int s_last;
    __shared__ double dsum[256];
    __threadfence();
    if (tid == 0) s_last = (atomicAdd(&g_done, 1) == GRID_FIX - 1);
    __syncthreads();
    if (s_last) {
        double acc = 0.0;
        for (int i = tid; i < NTILES; i += 256) acc += g_part[i];
        dsum[tid] = acc;
        __syncthreads();
        for (int off = 128; off > 0; off >>= 1) {
            if (tid < off) dsum[tid] += dsum[tid + off];
            __syncthreads();
        }
        if (tid == 0) {
            float m = (float)(dsum[0] / 8388608.0);
            loss_out[0] = __fadd_rn(m, __fmul_rn(0.25f, m));
        }
    }
}

extern "C" void kernel_launch(void* const* d_in, const int* in_sizes, int n_in,
                              void* d_out, int out_size) {
    const float* x  = (const float*)d_in[0];
    const float* cb = (const float*)d_in[1];
    float* out = (float*)d_out;

    cudaFuncSetAttribute(vq_main, cudaFuncAttributeMaxDynamicSharedMemorySize, SMEM_MAIN);
    vq_prep<<<64, 256>>>(cb);
    vq_main<<<GRID_MAIN, 256, SMEM_MAIN>>>(x, cb, out);
    vq_fixup<<<GRID_FIX, 256>>>(x, cb, out + (out_size - 1));
}